// round 4
// baseline (speedup 1.0000x reference)
#include <cuda_runtime.h>

// Scratch: per-node collapsed features (A, B, T, pad). 100000 nodes max.
#define MAX_NODES 100352
__device__ float4 g_node[MAX_NODES];

// ---------------------------------------------------------------------------
// node_kernel: per-block constant precompute (smem) + per-node collapse.
//   h0 = x·W1[:,0]+b1[0]; h1 = x·W1[:,1]+b1[1]; T = x·g + gb
//   A = h0*w0 + h1*w1;  B = h0*w1 - h1*w0
//   out[i] = h·Wout + bout = A + T + bout   (wait: h·Wout = h0*w0+h1*w1+T = A+T)
// ---------------------------------------------------------------------------
__global__ void node_kernel(const float4* __restrict__ x4,
                            const float* __restrict__ W1,
                            const float* __restrict__ b1,
                            const float* __restrict__ Wout,
                            const float* __restrict__ bout,
                            float* __restrict__ out, int n, int hidden) {
    __shared__ float red[5][128];
    __shared__ float sc[18];
    int k = threadIdx.x;

    // --- constant precompute: g_j = sum_{t>=2} W1[j,t]*Wout[t], gb = sum_{t>=2} b1[t]*Wout[t]
    if (k < 128) {
        float wk   = (k < hidden) ? Wout[k] : 0.f;
        float mask = (k >= 2) ? wk : 0.f;
        #pragma unroll
        for (int j = 0; j < 4; j++)
            red[j][k] = (k < hidden) ? mask * W1[j * hidden + k] : 0.f;
        red[4][k] = (k < hidden) ? mask * b1[k] : 0.f;
    }
    __syncthreads();
    #pragma unroll
    for (int s = 64; s > 0; s >>= 1) {
        if (k < s) {
            #pragma unroll
            for (int j = 0; j < 5; j++) red[j][k] += red[j][k + s];
        }
        __syncthreads();
    }
    if (k == 0) {
        sc[0] = Wout[0];
        sc[1] = Wout[1];
        #pragma unroll
        for (int j = 0; j < 4; j++) {
            sc[2 + j]  = W1[j * hidden + 0];
            sc[7 + j]  = W1[j * hidden + 1];
            sc[12 + j] = red[j][0];
        }
        sc[6]  = b1[0];
        sc[11] = b1[1];
        sc[16] = red[4][0];
        sc[17] = bout[0];
    }
    __syncthreads();

    int i = blockIdx.x * blockDim.x + threadIdx.x;
    if (i >= n) return;

    float c0  = sc[0],  c1  = sc[1];
    float a0  = sc[2],  a1  = sc[3],  a2  = sc[4],  a3  = sc[5],  b10 = sc[6];
    float d0  = sc[7],  d1  = sc[8],  d2  = sc[9],  d3  = sc[10], b11 = sc[11];
    float g0  = sc[12], g1  = sc[13], g2  = sc[14], g3  = sc[15];
    float gb  = sc[16], bo  = sc[17];

    float4 xv = x4[i];
    float h0 = fmaf(xv.x, a0, fmaf(xv.y, a1, fmaf(xv.z, a2, fmaf(xv.w, a3, b10))));
    float h1 = fmaf(xv.x, d0, fmaf(xv.y, d1, fmaf(xv.z, d2, fmaf(xv.w, d3, b11))));
    float T  = fmaf(xv.x, g0, fmaf(xv.y, g1, fmaf(xv.z, g2, fmaf(xv.w, g3, gb))));
    float A  = fmaf(h0, c0, h1 * c1);
    float B  = fmaf(h0, c1, -h1 * c0);

    g_node[i] = make_float4(A, B, T, 0.f);
    out[i] = A + T + bo;
}

// ---------------------------------------------------------------------------
// edge_kernel: 4 edges per thread, vectorized streams, 8 L2 gathers in flight.
// Per edge e=(u,v), phase p:
//   out[v] += c*A_u + s*B_u + T_u
//   out[u] += c*A_v - s*B_v + T_v
// ---------------------------------------------------------------------------
__device__ __forceinline__ void edge_accum(int u, int v, float s, float c,
                                           float* __restrict__ out) {
    float4 nu = g_node[u];
    float4 nv = g_node[v];
    atomicAdd(out + v, fmaf(c, nu.x, fmaf(s,  nu.y, nu.z)));
    atomicAdd(out + u, fmaf(c, nv.x, fmaf(-s, nv.y, nv.z)));
}

__global__ void edge_kernel4(const int4* __restrict__ edges2,   // 2 edges per int4
                             const float4* __restrict__ phases4,
                             const int2* __restrict__ edges,
                             const float* __restrict__ phases,
                             float* __restrict__ out, int m) {
    int t = blockIdx.x * blockDim.x + threadIdx.x;
    int base = t * 4;
    if (base + 3 < m) {
        int4 e01 = edges2[2 * t];
        int4 e23 = edges2[2 * t + 1];
        float4 ph = phases4[t];

        // Issue all 8 gathers before consuming (compiler front-batches LDGs).
        float4 n0u = g_node[e01.x], n0v = g_node[e01.y];
        float4 n1u = g_node[e01.z], n1v = g_node[e01.w];
        float4 n2u = g_node[e23.x], n2v = g_node[e23.y];
        float4 n3u = g_node[e23.z], n3v = g_node[e23.w];

        float s0, c0, s1, c1, s2, c2, s3, c3;
        __sincosf(ph.x, &s0, &c0);
        __sincosf(ph.y, &s1, &c1);
        __sincosf(ph.z, &s2, &c2);
        __sincosf(ph.w, &s3, &c3);

        atomicAdd(out + e01.y, fmaf(c0, n0u.x, fmaf(s0,  n0u.y, n0u.z)));
        atomicAdd(out + e01.x, fmaf(c0, n0v.x, fmaf(-s0, n0v.y, n0v.z)));
        atomicAdd(out + e01.w, fmaf(c1, n1u.x, fmaf(s1,  n1u.y, n1u.z)));
        atomicAdd(out + e01.z, fmaf(c1, n1v.x, fmaf(-s1, n1v.y, n1v.z)));
        atomicAdd(out + e23.y, fmaf(c2, n2u.x, fmaf(s2,  n2u.y, n2u.z)));
        atomicAdd(out + e23.x, fmaf(c2, n2v.x, fmaf(-s2, n2v.y, n2v.z)));
        atomicAdd(out + e23.w, fmaf(c3, n3u.x, fmaf(s3,  n3u.y, n3u.z)));
        atomicAdd(out + e23.z, fmaf(c3, n3v.x, fmaf(-s3, n3v.y, n3v.z)));
    } else if (base < m) {
        for (int e = base; e < m; e++) {
            int2 ed = edges[e];
            float s, c;
            __sincosf(phases[e], &s, &c);
            edge_accum(ed.x, ed.y, s, c, out);
        }
    }
}

extern "C" void kernel_launch(void* const* d_in, const int* in_sizes, int n_in,
                              void* d_out, int out_size) {
    const float* x      = (const float*)d_in[0];
    const int*   edges  = (const int*)  d_in[1];
    const float* W1     = (const float*)d_in[2];
    const float* b1     = (const float*)d_in[3];
    const float* phases = (const float*)d_in[4];
    const float* Wout   = (const float*)d_in[5];
    const float* bout   = (const float*)d_in[6];
    float* out = (float*)d_out;

    int hidden = in_sizes[3];          // 64
    int n = in_sizes[0] / 4;           // nodes (IN_DIM = 4)
    int m = in_sizes[1] / 2;           // edges

    node_kernel<<<(n + 255) / 256, 256>>>((const float4*)x, W1, b1, Wout, bout,
                                          out, n, hidden);

    int nthreads = (m + 3) / 4;
    edge_kernel4<<<(nthreads + 255) / 256, 256>>>((const int4*)edges,
                                                  (const float4*)phases,
                                                  (const int2*)edges, phases,
                                                  out, m);
}

// round 5
// speedup vs baseline: 1.0906x; 1.0906x over previous
#include <cuda_runtime.h>

// Scratch: per-node collapsed features (A, B, T, pad). 100000 nodes max.
#define MAX_NODES 100352
__device__ float4 g_node[MAX_NODES];

// ---------------------------------------------------------------------------
// node_kernel: per-block constant precompute (smem) + per-node collapse.
//   h0 = x·W1[:,0]+b1[0]; h1 = x·W1[:,1]+b1[1]; T = x·g + gb
//   A = h0*w0 + h1*w1;  B = h0*w1 - h1*w0
//   out[i] = h·Wout + bout = A + T + bout
// ---------------------------------------------------------------------------
__global__ void node_kernel(const float4* __restrict__ x4,
                            const float* __restrict__ W1,
                            const float* __restrict__ b1,
                            const float* __restrict__ Wout,
                            const float* __restrict__ bout,
                            float* __restrict__ out, int n, int hidden) {
    __shared__ float red[5][128];
    __shared__ float sc[18];
    int k = threadIdx.x;

    // --- constant precompute: g_j = sum_{t>=2} W1[j,t]*Wout[t], gb = sum_{t>=2} b1[t]*Wout[t]
    if (k < 128) {
        float wk   = (k < hidden) ? Wout[k] : 0.f;
        float mask = (k >= 2) ? wk : 0.f;
        #pragma unroll
        for (int j = 0; j < 4; j++)
            red[j][k] = (k < hidden) ? mask * W1[j * hidden + k] : 0.f;
        red[4][k] = (k < hidden) ? mask * b1[k] : 0.f;
    }
    __syncthreads();
    #pragma unroll
    for (int s = 64; s > 0; s >>= 1) {
        if (k < s) {
            #pragma unroll
            for (int j = 0; j < 5; j++) red[j][k] += red[j][k + s];
        }
        __syncthreads();
    }
    if (k == 0) {
        sc[0] = Wout[0];
        sc[1] = Wout[1];
        #pragma unroll
        for (int j = 0; j < 4; j++) {
            sc[2 + j]  = W1[j * hidden + 0];
            sc[7 + j]  = W1[j * hidden + 1];
            sc[12 + j] = red[j][0];
        }
        sc[6]  = b1[0];
        sc[11] = b1[1];
        sc[16] = red[4][0];
        sc[17] = bout[0];
    }
    __syncthreads();

    int i = blockIdx.x * blockDim.x + threadIdx.x;
    if (i >= n) return;

    float c0  = sc[0],  c1  = sc[1];
    float a0  = sc[2],  a1  = sc[3],  a2  = sc[4],  a3  = sc[5],  b10 = sc[6];
    float d0  = sc[7],  d1  = sc[8],  d2  = sc[9],  d3  = sc[10], b11 = sc[11];
    float g0  = sc[12], g1  = sc[13], g2  = sc[14], g3  = sc[15];
    float gb  = sc[16], bo  = sc[17];

    float4 xv = x4[i];
    float h0 = fmaf(xv.x, a0, fmaf(xv.y, a1, fmaf(xv.z, a2, fmaf(xv.w, a3, b10))));
    float h1 = fmaf(xv.x, d0, fmaf(xv.y, d1, fmaf(xv.z, d2, fmaf(xv.w, d3, b11))));
    float T  = fmaf(xv.x, g0, fmaf(xv.y, g1, fmaf(xv.z, g2, fmaf(xv.w, g3, gb))));
    float A  = fmaf(h0, c0, h1 * c1);
    float B  = fmaf(h0, c1, -h1 * c0);

    g_node[i] = make_float4(A, B, T, 0.f);
    out[i] = A + T + bo;
}

// ---------------------------------------------------------------------------
// edge_kernel: ONE edge per thread — maximize concurrent warps to hide the
// edge-load -> gather -> atomic dependency chain. launch_bounds(256, 8)
// forces <=32 regs so the register file admits the full 64 warps/SM.
// Per edge e=(u,v), phase p:
//   out[v] += c*A_u + s*B_u + T_u
//   out[u] += c*A_v - s*B_v + T_v
// ---------------------------------------------------------------------------
__global__ void __launch_bounds__(256, 8)
edge_kernel(const int2* __restrict__ edges,
            const float* __restrict__ phases,
            float* __restrict__ out, int m) {
    int e = blockIdx.x * blockDim.x + threadIdx.x;
    if (e >= m) return;
    int2 ed = edges[e];
    float p = phases[e];
    float4 nu = g_node[ed.x];   // source features
    float4 nv = g_node[ed.y];   // dest features
    float s, c;
    __sincosf(p, &s, &c);
    atomicAdd(out + ed.y, fmaf(c, nu.x, fmaf(s,  nu.y, nu.z)));
    atomicAdd(out + ed.x, fmaf(c, nv.x, fmaf(-s, nv.y, nv.z)));
}

extern "C" void kernel_launch(void* const* d_in, const int* in_sizes, int n_in,
                              void* d_out, int out_size) {
    const float* x      = (const float*)d_in[0];
    const int*   edges  = (const int*)  d_in[1];
    const float* W1     = (const float*)d_in[2];
    const float* b1     = (const float*)d_in[3];
    const float* phases = (const float*)d_in[4];
    const float* Wout   = (const float*)d_in[5];
    const float* bout   = (const float*)d_in[6];
    float* out = (float*)d_out;

    int hidden = in_sizes[3];          // 64
    int n = in_sizes[0] / 4;           // nodes (IN_DIM = 4)
    int m = in_sizes[1] / 2;           // edges

    node_kernel<<<(n + 255) / 256, 256>>>((const float4*)x, W1, b1, Wout, bout,
                                          out, n, hidden);

    edge_kernel<<<(m + 255) / 256, 256>>>((const int2*)edges, phases, out, m);
}

// round 6
// speedup vs baseline: 1.0920x; 1.0013x over previous
#include <cuda_runtime.h>

// Scratch: per-node collapsed features (A, B, T, pad). 100000 nodes max.
#define MAX_NODES 100352
__device__ float4 g_node[MAX_NODES];

// ---------------------------------------------------------------------------
// node_kernel: warp-redundant constant precompute (no smem, no barriers)
//   g_j = sum_{t>=2} W1[j,t]*Wout[t],  gb = sum_{t>=2} b1[t]*Wout[t]
// then per-node collapse:
//   h0 = x·W1[:,0]+b1[0]; h1 = x·W1[:,1]+b1[1]; T = x·g + gb
//   A = w0*h0 + w1*h1;  B = w1*h0 - w0*h1
//   out[i] = A + T + bout
// ---------------------------------------------------------------------------
__global__ void node_kernel(const float4* __restrict__ x4,
                            const float* __restrict__ W1,
                            const float* __restrict__ b1,
                            const float* __restrict__ Wout,
                            const float* __restrict__ bout,
                            float* __restrict__ out, int n, int hidden) {
    int lane = threadIdx.x & 31;

    // Each warp redundantly reduces the 5 constant sums via shuffles.
    float s0 = 0.f, s1 = 0.f, s2 = 0.f, s3 = 0.f, s4 = 0.f;
    for (int t = lane; t < hidden; t += 32) {
        float wk = __ldg(Wout + t);
        float mask = (t >= 2) ? wk : 0.f;
        s0 = fmaf(mask, __ldg(W1 + 0 * hidden + t), s0);
        s1 = fmaf(mask, __ldg(W1 + 1 * hidden + t), s1);
        s2 = fmaf(mask, __ldg(W1 + 2 * hidden + t), s2);
        s3 = fmaf(mask, __ldg(W1 + 3 * hidden + t), s3);
        s4 = fmaf(mask, __ldg(b1 + t), s4);
    }
    #pragma unroll
    for (int off = 16; off > 0; off >>= 1) {
        s0 += __shfl_xor_sync(0xFFFFFFFF, s0, off);
        s1 += __shfl_xor_sync(0xFFFFFFFF, s1, off);
        s2 += __shfl_xor_sync(0xFFFFFFFF, s2, off);
        s3 += __shfl_xor_sync(0xFFFFFFFF, s3, off);
        s4 += __shfl_xor_sync(0xFFFFFFFF, s4, off);
    }

    int i = blockIdx.x * blockDim.x + threadIdx.x;
    if (i >= n) return;

    float c0  = __ldg(Wout + 0), c1 = __ldg(Wout + 1);
    float a0  = __ldg(W1 + 0 * hidden), a1 = __ldg(W1 + 1 * hidden);
    float a2  = __ldg(W1 + 2 * hidden), a3 = __ldg(W1 + 3 * hidden);
    float d0  = __ldg(W1 + 0 * hidden + 1), d1 = __ldg(W1 + 1 * hidden + 1);
    float d2  = __ldg(W1 + 2 * hidden + 1), d3 = __ldg(W1 + 3 * hidden + 1);
    float b10 = __ldg(b1 + 0), b11 = __ldg(b1 + 1);
    float bo  = __ldg(bout);

    float4 xv = x4[i];
    float h0 = fmaf(xv.x, a0, fmaf(xv.y, a1, fmaf(xv.z, a2, fmaf(xv.w, a3, b10))));
    float h1 = fmaf(xv.x, d0, fmaf(xv.y, d1, fmaf(xv.z, d2, fmaf(xv.w, d3, b11))));
    float T  = fmaf(xv.x, s0, fmaf(xv.y, s1, fmaf(xv.z, s2, fmaf(xv.w, s3, s4))));
    float A  = fmaf(h0, c0, h1 * c1);
    float B  = fmaf(h0, c1, -h1 * c0);

    g_node[i] = make_float4(A, B, T, 0.f);
    out[i] = A + T + bo;
}

// ---------------------------------------------------------------------------
// edge_kernel2: TWO edges per thread, <=32 regs (launch_bounds(256,8)) so the
// RF still admits 64 warps/SM, with 4 independent gathers in flight per thread.
// Per edge e=(u,v), phase p:
//   out[v] += c*A_u + s*B_u + T_u
//   out[u] += c*A_v - s*B_v + T_v
// ---------------------------------------------------------------------------
__global__ void __launch_bounds__(256, 8)
edge_kernel2(const int4* __restrict__ edges2,     // 2 edges per int4
             const float2* __restrict__ phases2,  // 2 phases per float2
             const int2* __restrict__ edges,
             const float* __restrict__ phases,
             float* __restrict__ out, int m) {
    int t = blockIdx.x * blockDim.x + threadIdx.x;
    int base = t * 2;
    if (base + 1 < m) {
        int4   e  = edges2[t];
        float2 ph = phases2[t];

        // 4 independent L2 gathers in flight before any consumption.
        float4 n0u = __ldg(&g_node[e.x]);
        float4 n0v = __ldg(&g_node[e.y]);
        float4 n1u = __ldg(&g_node[e.z]);
        float4 n1v = __ldg(&g_node[e.w]);

        float s0, c0, s1, c1;
        __sincosf(ph.x, &s0, &c0);
        __sincosf(ph.y, &s1, &c1);

        atomicAdd(out + e.y, fmaf(c0, n0u.x, fmaf(s0,  n0u.y, n0u.z)));
        atomicAdd(out + e.x, fmaf(c0, n0v.x, fmaf(-s0, n0v.y, n0v.z)));
        atomicAdd(out + e.w, fmaf(c1, n1u.x, fmaf(s1,  n1u.y, n1u.z)));
        atomicAdd(out + e.z, fmaf(c1, n1v.x, fmaf(-s1, n1v.y, n1v.z)));
    } else if (base < m) {
        // tail: one edge
        int2 ed = edges[base];
        float s, c;
        __sincosf(phases[base], &s, &c);
        float4 nu = __ldg(&g_node[ed.x]);
        float4 nv = __ldg(&g_node[ed.y]);
        atomicAdd(out + ed.y, fmaf(c, nu.x, fmaf(s,  nu.y, nu.z)));
        atomicAdd(out + ed.x, fmaf(c, nv.x, fmaf(-s, nv.y, nv.z)));
    }
}

extern "C" void kernel_launch(void* const* d_in, const int* in_sizes, int n_in,
                              void* d_out, int out_size) {
    const float* x      = (const float*)d_in[0];
    const int*   edges  = (const int*)  d_in[1];
    const float* W1     = (const float*)d_in[2];
    const float* b1     = (const float*)d_in[3];
    const float* phases = (const float*)d_in[4];
    const float* Wout   = (const float*)d_in[5];
    const float* bout   = (const float*)d_in[6];
    float* out = (float*)d_out;

    int hidden = in_sizes[3];          // 64
    int n = in_sizes[0] / 4;           // nodes (IN_DIM = 4)
    int m = in_sizes[1] / 2;           // edges

    node_kernel<<<(n + 255) / 256, 256>>>((const float4*)x, W1, b1, Wout, bout,
                                          out, n, hidden);

    int nthreads = (m + 1) / 2;
    edge_kernel2<<<(nthreads + 255) / 256, 256>>>((const int4*)edges,
                                                  (const float2*)phases,
                                                  (const int2*)edges, phases,
                                                  out, m);
}